// round 14
// baseline (speedup 1.0000x reference)
#include <cuda_runtime.h>
#include <cstdint>

#define T 128
#define N 1024
#define CSZ 8            // cluster size == grid size (one cluster)
#define LOCR 128         // rows/cols owned per block (N/CSZ)
#define NTHR 1024
#define LMBDA 0.01f
#define PAD 136          // 136 % 32 == 8: conflict-free row & column passes

// ---------------- device scratch (no allocations allowed) ----------------
__device__ float g_Fx[T * N];   // precomputed F @ x_t, [t][i]
__device__ float g_Sx[T];       // precomputed sum(x_t)

// ---------------- smem layout (float offsets) ----------------------------
#define OFF_A    0                        // At[i][s] 128*136 = 17408
#define OFF_B    (OFF_A + 128 * PAD)      // Bt[j][s] 17408
#define OFF_X    (OFF_B + 128 * PAD)
#define OFF_FX   (OFF_X + 128)
#define OFF_SX   (OFF_FX + 128)
#define OFF_U    (OFF_SX + 128)
#define OFF_W    (OFF_U + 128)
#define OFF_Z    (OFF_W + 128)
#define OFF_CS   (OFF_Z + 128)            // col scales c_j this step
#define OFF_RS   (OFF_CS + 128)           // row scales r_i this step
#define OFF_EXU  (OFF_RS + 128)           // [8][128] slice partials
#define OFF_EXW  (OFF_EXU + 1024)
#define OFF_EXZ  (OFF_EXW + 1024)
#define OFF_UW2  (OFF_EXZ + 1024)         // [par][128] float2 = 512 f
#define OFF_ZL   (OFF_UW2 + 512)          // [par][128] = 256 f
#define SMEM_FLOATS (OFF_ZL + 256)
#define SMEM_BYTES  (SMEM_FLOATS * 4)     // ~156 KB

// ---------------- cluster / DSMEM helpers --------------------------------
__device__ __forceinline__ uint32_t s2u(const void* p) {
    uint32_t a;
    asm("{ .reg .u64 t; cvta.to.shared.u64 t, %1; cvt.u32.u64 %0, t; }"
        : "=r"(a) : "l"(p));
    return a;
}
__device__ __forceinline__ float ld_peer(uint32_t saddr, uint32_t rank) {
    uint32_t ra; float v;
    asm volatile("mapa.shared::cluster.u32 %0, %1, %2;" : "=r"(ra) : "r"(saddr), "r"(rank));
    asm volatile("ld.shared::cluster.f32 %0, [%1];" : "=f"(v) : "r"(ra));
    return v;
}
__device__ __forceinline__ float2 ld_peer_v2(uint32_t saddr, uint32_t rank) {
    uint32_t ra; float2 v;
    asm volatile("mapa.shared::cluster.u32 %0, %1, %2;" : "=r"(ra) : "r"(saddr), "r"(rank));
    asm volatile("ld.shared::cluster.v2.f32 {%0,%1}, [%2];"
                 : "=f"(v.x), "=f"(v.y) : "r"(ra));
    return v;
}
#define CLUSTER_SYNC() do { \
    asm volatile("barrier.cluster.arrive.aligned;" ::: "memory"); \
    asm volatile("barrier.cluster.wait.aligned;"   ::: "memory"); \
} while (0)

__device__ __forceinline__ float grp8_sum(float v) {
    v += __shfl_xor_sync(0xFFFFFFFFu, v, 1);
    v += __shfl_xor_sync(0xFFFFFFFFu, v, 2);
    v += __shfl_xor_sync(0xFFFFFFFFu, v, 4);
    return v;
}

// ---------------- prologue: Sx[t] = sum_j X[t][j] ------------------------
__global__ void sx_kernel(const float* __restrict__ X) {
    int t = blockIdx.x, l = threadIdx.x;
    float s = 0.0f;
    for (int k = l; k < N; k += 32) s += X[t * N + k];
    #pragma unroll
    for (int o = 16; o; o >>= 1) s += __shfl_xor_sync(0xFFFFFFFFu, s, o);
    if (l == 0) g_Sx[t] = s;
}

// ---------------- prologue: Fx[t][i] = sum_k F[i][k] * X[t][k] -----------
__global__ void gemm_fx(const float* __restrict__ F, const float* __restrict__ X) {
    __shared__ float Ft[32][33];
    __shared__ float Xt[32][33];
    int ib = blockIdx.x, tb = blockIdx.y;
    int tid = threadIdx.x;
    int il = tid & 31;
    int tg = tid >> 5;
    float acc[4] = {0.f, 0.f, 0.f, 0.f};
    for (int kk = 0; kk < N; kk += 32) {
        #pragma unroll
        for (int q = 0; q < 4; q++) {
            int idx = tid + 256 * q;
            int r = idx >> 5, c = idx & 31;
            Ft[r][c] = F[(ib * 32 + r) * N + kk + c];
            Xt[r][c] = X[(tb * 32 + r) * N + kk + c];
        }
        __syncthreads();
        #pragma unroll
        for (int k = 0; k < 32; k++) {
            float f = Ft[il][k];
            #pragma unroll
            for (int m = 0; m < 4; m++)
                acc[m] = fmaf(f, Xt[tg + 8 * m][k], acc[m]);
        }
        __syncthreads();
    }
    #pragma unroll
    for (int m = 0; m < 4; m++)
        g_Fx[(tb * 32 + tg + 8 * m) * N + ib * 32 + il] = acc[m];
}

// ---------------- main low-rank scan: 1 cluster, CSYNC skeleton ----------
// P = At Bt^T in current units. Per step: deferred col renorm (c from z),
// append x; bounded uw column pass applies c; CSYNC; parallel pull-reduce;
// A row phase -> out, r; bounded z pass applies r; CSYNC; z pulled at t+1.
__global__ __launch_bounds__(NTHR, 1) __cluster_dims__(CSZ, 1, 1)
void rf_lr(const float* __restrict__ X, float* __restrict__ out) {
    extern __shared__ float sm[];
    float* At = sm + OFF_A;
    float* Bt = sm + OFF_B;

    const int tid = threadIdx.x;
    const int blk = blockIdx.x;         // == cluster rank
    const int rr  = tid >> 3;           // row in row phases
    const int sub = tid & 7;            // sub-lane in row group
    const int h   = tid >> 7;           // slice (0..7) in column passes
    const int sc  = tid & 127;          // s index in column passes
    const int ps  = tid >> 3;           // s index in pull phases
    const int pr  = tid & 7;            // rank index in pull phases

    for (int i = tid; i < SMEM_FLOATS; i += NTHR) sm[i] = 0.0f;
    if (tid < 128) sm[OFF_SX + tid] = g_Sx[tid];
    __syncthreads();
    CLUSTER_SYNC();     // peers zeroed before any remote access

    float x_n = 0.0f, fx_n = 0.0f;
    if (tid < 128) {
        x_n  = X[blk * LOCR + tid];
        fx_n = g_Fx[blk * LOCR + tid];
    }

    for (int t = 0; t < T; t++) {
        const int par = t & 1;

        // ---- stage x/Fx; parallel pull + reduce z(t-1) ------------------
        if (tid < 128) {
            sm[OFF_X + tid]  = x_n;
            sm[OFF_FX + tid] = fx_n;
        }
        {
            float z = 0.0f;
            if (t > 0 && ps < t) {
                const int zp = (t - 1) & 1;
                z = ld_peer(s2u(&sm[OFF_ZL + zp * 128 + ps]), pr);
            }
            z += __shfl_xor_sync(0xFFFFFFFFu, z, 1);
            z += __shfl_xor_sync(0xFFFFFFFFu, z, 2);
            z += __shfl_xor_sync(0xFFFFFFFFu, z, 4);
            if (t > 0 && ps < t && pr == 0) sm[OFF_Z + ps] = z;
        }
        __syncthreads();                                   // BAR1

        // ---- B row phase: colsum -> c_j ; append x_t --------------------
        {
            float cs = 0.0f;
            for (int s = sub; s < t; s += 8)
                cs = fmaf(Bt[rr * PAD + s], sm[OFF_Z + s], cs);
            cs = grp8_sum(cs);
            if (sub == 0) {
                sm[OFF_CS + rr] = (cs > 1.0f) ? (1.0f / cs) : 1.0f;
                Bt[rr * PAD + t] = sm[OFF_X + rr];
            }
        }
        __syncthreads();                                   // BAR2

        // ---- uw column pass (s<t only): apply c + writeback -------------
        if (sc < t) {
            float up = 0.0f, wp = 0.0f;
            const int j0 = h * 16;
            #pragma unroll 4
            for (int j = j0; j < j0 + 16; j++) {
                const float v = Bt[j * PAD + sc] * sm[OFF_CS + j];
                Bt[j * PAD + sc] = v;
                up = fmaf(v, sm[OFF_X + j], up);
                wp += v;
            }
            sm[OFF_EXU + h * 128 + sc] = up;
            sm[OFF_EXW + h * 128 + sc] = wp;
        }
        if (t + 1 < T && tid < 128) {                      // overlap prefetch
            x_n  = X[(t + 1) * N + blk * LOCR + tid];
            fx_n = g_Fx[(t + 1) * N + blk * LOCR + tid];
        }
        __syncthreads();                                   // BAR3

        // ---- local pre-reduce uw -> exchange slot -----------------------
        if (tid < t) {
            float u = 0.0f, w = 0.0f;
            #pragma unroll
            for (int hh = 0; hh < 8; hh++) {
                u += sm[OFF_EXU + hh * 128 + tid];
                w += sm[OFF_EXW + hh * 128 + tid];
            }
            *reinterpret_cast<float2*>(&sm[OFF_UW2 + par * 256 + tid * 2]) =
                make_float2(u, w);
        }
        CLUSTER_SYNC();                                    // release + acquire

        // ---- parallel pull + reduce uw ----------------------------------
        {
            float u = 0.0f, w = 0.0f;
            if (ps < t) {
                const float2 v =
                    ld_peer_v2(s2u(&sm[OFF_UW2 + par * 256 + ps * 2]), pr);
                u = v.x; w = v.y;
            }
            u += __shfl_xor_sync(0xFFFFFFFFu, u, 1);
            u += __shfl_xor_sync(0xFFFFFFFFu, u, 2);
            u += __shfl_xor_sync(0xFFFFFFFFu, u, 4);
            w += __shfl_xor_sync(0xFFFFFFFFu, w, 1);
            w += __shfl_xor_sync(0xFFFFFFFFu, w, 2);
            w += __shfl_xor_sync(0xFFFFFFFFu, w, 4);
            if (ps < t && pr == 0) {
                sm[OFF_U + ps] = u;
                sm[OFF_W + ps] = w;
            }
        }
        __syncthreads();                                   // BAR4

        // ---- A row phase: out, r_i, append ------------------------------
        {
            float p = 0.0f, q = 0.0f;
            for (int s = sub; s < t; s += 8) {
                const float a = At[rr * PAD + s];
                p = fmaf(a, sm[OFF_U + s], p);
                q = fmaf(a, sm[OFF_W + s], q);
            }
            p = grp8_sum(p);
            q = grp8_sum(q);
            const float outv = sm[OFF_FX + rr] + p;
            if (sub == 0) {
                out[t * N + blk * LOCR + rr] = outv;
                if (t < T - 1) {
                    const float rs = fmaf(LMBDA * outv, sm[OFF_SX + t], q);
                    sm[OFF_RS + rr]  = (rs > 1.0f) ? (1.0f / rs) : 1.0f;
                    At[rr * PAD + t] = LMBDA * outv;   // z pass applies r
                }
            }
        }
        if (t == T - 1) break;
        __syncthreads();                                   // BAR5

        // ---- z column pass (s<=t): apply r + writeback ------------------
        if (sc <= t) {
            float zp = 0.0f;
            const int i0 = h * 16;
            #pragma unroll 4
            for (int i = i0; i < i0 + 16; i++) {
                const float v = At[i * PAD + sc] * sm[OFF_RS + i];
                At[i * PAD + sc] = v;
                zp += v;
            }
            sm[OFF_EXZ + h * 128 + sc] = zp;
        }
        __syncthreads();                                   // BAR6

        // ---- local pre-reduce z -> exchange slot ------------------------
        if (tid <= t) {
            float z = 0.0f;
            #pragma unroll
            for (int hh = 0; hh < 8; hh++) z += sm[OFF_EXZ + hh * 128 + tid];
            sm[OFF_ZL + par * 128 + tid] = z;
        }
        CLUSTER_SYNC();                                    // z visible cluster-wide
        // consumers pull at top of step t+1
    }

    CLUSTER_SYNC();   // no CTA exits while peers may still pull from it
}

// ---------------- launch ---------------------------------------------------
extern "C" void kernel_launch(void* const* d_in, const int* in_sizes, int n_in,
                              void* d_out, int out_size) {
    // inputs [T*N]; in_in_fixed [N*N] (dead); out_in_fixed [N*N] (last)
    const float* X = nullptr;
    const float* F = nullptr;
    for (int i = 0; i < n_in; i++) {
        if (in_sizes[i] == T * N && X == nullptr) X = (const float*)d_in[i];
        if (in_sizes[i] == N * N) F = (const float*)d_in[i];
    }
    float* out = (float*)d_out;

    static bool attr_set = false;
    if (!attr_set) {
        cudaFuncSetAttribute(rf_lr, cudaFuncAttributeMaxDynamicSharedMemorySize,
                             SMEM_BYTES);
        attr_set = true;
    }

    sx_kernel<<<T, 32>>>(X);
    dim3 g(N / 32, T / 32);
    gemm_fx<<<g, 256>>>(F, X);
    rf_lr<<<CSZ, NTHR, SMEM_BYTES>>>(X, out);
}

// round 17
// speedup vs baseline: 1.2427x; 1.2427x over previous
#include <cuda_runtime.h>
#include <cstdint>

#define T 128
#define N 1024
#define CSZ 8            // cluster size == grid size (one cluster)
#define LOCR 128         // rows/cols owned per block (N/CSZ)
#define NTHR 1024
#define LMBDA 0.01f
#define PAD 136          // 136 % 32 == 8: conflict-free row & column passes

// ---------------- device scratch (no allocations allowed) ----------------
__device__ float g_Fx[T * N];   // precomputed F @ x_t, [t][i]
__device__ float g_Sx[T];       // precomputed sum(x_t)

// ---------------- smem layout (float offsets) ----------------------------
#define OFF_A    0                        // At[i][s] 128*136 = 17408
#define OFF_B    (OFF_A + 128 * PAD)      // Bt[j][s] 17408
#define OFF_X    (OFF_B + 128 * PAD)
#define OFF_FX   (OFF_X + 128)
#define OFF_SX   (OFF_FX + 128)
#define OFF_U    (OFF_SX + 128)
#define OFF_W    (OFF_U + 128)
#define OFF_Z    (OFF_W + 128)
#define OFF_EXU  (OFF_Z + 128)            // [8][128] slice partials
#define OFF_EXW  (OFF_EXU + 1024)
#define OFF_EXZ  (OFF_EXW + 1024)
#define OFF_UW2  (OFF_EXZ + 1024)         // [par][128] float2 = 512 f
#define OFF_ZL   (OFF_UW2 + 512)          // [par][128] = 256 f
#define SMEM_FLOATS (OFF_ZL + 256)
#define SMEM_BYTES  (SMEM_FLOATS * 4)

// ---------------- cluster / DSMEM helpers --------------------------------
__device__ __forceinline__ uint32_t s2u(const void* p) {
    uint32_t a;
    asm("{ .reg .u64 t; cvta.to.shared.u64 t, %1; cvt.u32.u64 %0, t; }"
        : "=r"(a) : "l"(p));
    return a;
}
__device__ __forceinline__ float ld_peer(uint32_t saddr, uint32_t rank) {
    uint32_t ra; float v;
    asm volatile("mapa.shared::cluster.u32 %0, %1, %2;" : "=r"(ra) : "r"(saddr), "r"(rank));
    asm volatile("ld.shared::cluster.f32 %0, [%1];" : "=f"(v) : "r"(ra));
    return v;
}
__device__ __forceinline__ float2 ld_peer_v2(uint32_t saddr, uint32_t rank) {
    uint32_t ra; float2 v;
    asm volatile("mapa.shared::cluster.u32 %0, %1, %2;" : "=r"(ra) : "r"(saddr), "r"(rank));
    asm volatile("ld.shared::cluster.v2.f32 {%0,%1}, [%2];"
                 : "=f"(v.x), "=f"(v.y) : "r"(ra));
    return v;
}
#define CLUSTER_SYNC() do { \
    asm volatile("barrier.cluster.arrive.aligned;" ::: "memory"); \
    asm volatile("barrier.cluster.wait.aligned;"   ::: "memory"); \
} while (0)

__device__ __forceinline__ float grp8_sum(float v) {
    v += __shfl_xor_sync(0xFFFFFFFFu, v, 1);
    v += __shfl_xor_sync(0xFFFFFFFFu, v, 2);
    v += __shfl_xor_sync(0xFFFFFFFFu, v, 4);
    return v;
}

// ---------------- prologue: Sx[t] = sum_j X[t][j] ------------------------
__global__ void sx_kernel(const float* __restrict__ X) {
    int t = blockIdx.x, l = threadIdx.x;
    float s = 0.0f;
    for (int k = l; k < N; k += 32) s += X[t * N + k];
    #pragma unroll
    for (int o = 16; o; o >>= 1) s += __shfl_xor_sync(0xFFFFFFFFu, s, o);
    if (l == 0) g_Sx[t] = s;
}

// ---------------- prologue: Fx[t][i] = sum_k F[i][k] * X[t][k] -----------
__global__ void gemm_fx(const float* __restrict__ F, const float* __restrict__ X) {
    __shared__ float Ft[32][33];
    __shared__ float Xt[32][33];
    int ib = blockIdx.x, tb = blockIdx.y;
    int tid = threadIdx.x;
    int il = tid & 31;
    int tg = tid >> 5;
    float acc[4] = {0.f, 0.f, 0.f, 0.f};
    for (int kk = 0; kk < N; kk += 32) {
        #pragma unroll
        for (int q = 0; q < 4; q++) {
            int idx = tid + 256 * q;
            int r = idx >> 5, c = idx & 31;
            Ft[r][c] = F[(ib * 32 + r) * N + kk + c];
            Xt[r][c] = X[(tb * 32 + r) * N + kk + c];
        }
        __syncthreads();
        #pragma unroll
        for (int k = 0; k < 32; k++) {
            float f = Ft[il][k];
            #pragma unroll
            for (int m = 0; m < 4; m++)
                acc[m] = fmaf(f, Xt[tg + 8 * m][k], acc[m]);
        }
        __syncthreads();
    }
    #pragma unroll
    for (int m = 0; m < 4; m++)
        g_Fx[(tb * 32 + tg + 8 * m) * N + ib * 32 + il] = acc[m];
}

// ---------------- main low-rank scan: R11 skeleton + bounded passes ------
__global__ __launch_bounds__(NTHR, 1) __cluster_dims__(CSZ, 1, 1)
void rf_lr(const float* __restrict__ X, float* __restrict__ out) {
    extern __shared__ float sm[];
    float* At = sm + OFF_A;
    float* Bt = sm + OFF_B;

    const int tid = threadIdx.x;
    const int blk = blockIdx.x;         // == cluster rank
    const int rr  = tid >> 3;           // row in row phases
    const int sub = tid & 7;            // sub-lane in row group
    const int sc  = tid & 127;          // s index in column phases
    const int h   = tid >> 7;           // slice in column phases

    for (int i = tid; i < SMEM_FLOATS; i += NTHR) sm[i] = 0.0f;
    __syncthreads();
    if (tid < 128) sm[OFF_SX + tid] = g_Sx[tid];

    float x_n = 0.0f, fx_n = 0.0f;
    if (tid < 128) {
        x_n  = X[blk * LOCR + tid];
        fx_n = g_Fx[blk * LOCR + tid];
    }
    __syncthreads();
    CLUSTER_SYNC();     // peers zeroed before any remote access

    for (int t = 0; t < T; t++) {
        const int par = t & 1;

        // ---- stage prefetched x_t / Fx_t --------------------------------
        if (tid < 128) {
            sm[OFF_X + tid]  = x_n;
            sm[OFF_FX + tid] = fx_n;
        }
        __syncthreads();
        if (t + 1 < T && tid < 128) {
            x_n  = X[(t + 1) * N + blk * LOCR + tid];
            fx_n = g_Fx[(t + 1) * N + blk * LOCR + tid];
        }

        // ---- B row phase: finish step t-1 col renorm, append col t ------
        {
            if (t > 0) {
                float cs = 0.0f;
                #pragma unroll 4
                for (int s = sub; s < t; s += 8)
                    cs = fmaf(Bt[rr * PAD + s], sm[OFF_Z + s], cs);
                cs = grp8_sum(cs);
                if (cs > 1.0f) {
                    const float c = 1.0f / cs;
                    #pragma unroll 4
                    for (int s = sub; s < t; s += 8) Bt[rr * PAD + s] *= c;
                }
            }
            if (sub == 0) Bt[rr * PAD + t] = sm[OFF_X + rr];
        }
        __syncthreads();

        // ---- uw column pass (bounded: s < t) ----------------------------
        if (t > 0 && sc < t) {
            float up = 0.0f, wp = 0.0f;
            const int j0 = h * 16;
            #pragma unroll 4
            for (int j = j0; j < j0 + 16; j++) {
                const float b = Bt[j * PAD + sc];
                up = fmaf(b, sm[OFF_X + j], up);
                wp += b;
            }
            sm[OFF_EXU + h * 128 + sc] = up;
            sm[OFF_EXW + h * 128 + sc] = wp;
        }
        __syncthreads();
        if (t > 0 && tid < t) {
            float u = 0.0f, w = 0.0f;
            #pragma unroll
            for (int hh = 0; hh < 8; hh++) {
                u += sm[OFF_EXU + hh * 128 + tid];
                w += sm[OFF_EXW + hh * 128 + tid];
            }
            *reinterpret_cast<float2*>(&sm[OFF_UW2 + par * 256 + tid * 2]) =
                make_float2(u, w);
        }
        CLUSTER_SYNC();   // release + acquire
        if (t > 0 && tid < t) {
            float u = 0.0f, w = 0.0f;
            const uint32_t a = s2u(&sm[OFF_UW2 + par * 256 + tid * 2]);
            #pragma unroll
            for (int r0 = 0; r0 < CSZ; r0++) {
                const float2 v = ld_peer_v2(a, r0);
                u += v.x; w += v.y;
            }
            sm[OFF_U + tid] = u;
            sm[OFF_W + tid] = w;
        }
        __syncthreads();

        // ---- A row phase: out, append, row renorm -----------------------
        {
            float p = 0.0f, q = 0.0f;
            #pragma unroll 4
            for (int s = sub; s < t; s += 8) {
                const float a = At[rr * PAD + s];
                p = fmaf(a, sm[OFF_U + s], p);
                q = fmaf(a, sm[OFF_W + s], q);
            }
            p = grp8_sum(p);
            q = grp8_sum(q);
            const float outv = sm[OFF_FX + rr] + p;
            if (sub == 0) out[t * N + blk * LOCR + rr] = outv;
            if (t < T - 1) {
                const float rs = fmaf(LMBDA * outv, sm[OFF_SX + t], q);
                const float r  = (rs > 1.0f) ? (1.0f / rs) : 1.0f;
                #pragma unroll 4
                for (int s = sub; s < t; s += 8) At[rr * PAD + s] *= r;
                if (sub == (t & 7)) At[rr * PAD + t] = r * (LMBDA * outv);
            }
        }
        if (t == T - 1) break;
        __syncthreads();

        // ---- z column pass (bounded: s <= t) ----------------------------
        if (sc <= t) {
            float zp = 0.0f;
            const int i0 = h * 16;
            #pragma unroll 4
            for (int i = i0; i < i0 + 16; i++) zp += At[i * PAD + sc];
            sm[OFF_EXZ + h * 128 + sc] = zp;
        }
        __syncthreads();
        if (tid <= t) {
            float z = 0.0f;
            #pragma unroll
            for (int hh = 0; hh < 8; hh++) z += sm[OFF_EXZ + hh * 128 + tid];
            sm[OFF_ZL + par * 128 + tid] = z;
        }
        CLUSTER_SYNC();
        if (tid <= t) {
            float z = 0.0f;
            const uint32_t a = s2u(&sm[OFF_ZL + par * 128 + tid]);
            #pragma unroll
            for (int r0 = 0; r0 < CSZ; r0++) z += ld_peer(a, r0);
            sm[OFF_Z + tid] = z;
        }
        // next iteration's top __syncthreads orders Z for the B phase
    }

    CLUSTER_SYNC();   // no CTA exits while peers may still pull from it
}

// ---------------- launch ---------------------------------------------------
extern "C" void kernel_launch(void* const* d_in, const int* in_sizes, int n_in,
                              void* d_out, int out_size) {
    // inputs [T*N]; in_in_fixed [N*N] (dead); out_in_fixed [N*N] (last)
    const float* X = nullptr;
    const float* F = nullptr;
    for (int i = 0; i < n_in; i++) {
        if (in_sizes[i] == T * N && X == nullptr) X = (const float*)d_in[i];
        if (in_sizes[i] == N * N) F = (const float*)d_in[i];
    }
    float* out = (float*)d_out;

    static bool attr_set = false;
    if (!attr_set) {
        cudaFuncSetAttribute(rf_lr, cudaFuncAttributeMaxDynamicSharedMemorySize,
                             SMEM_BYTES);
        attr_set = true;
    }

    sx_kernel<<<T, 32>>>(X);
    dim3 g(N / 32, T / 32);
    gemm_fx<<<g, 256>>>(F, X);
    rf_lr<<<CSZ, NTHR, SMEM_BYTES>>>(X, out);
}